// round 8
// baseline (speedup 1.0000x reference)
#include <cuda_runtime.h>
#include <cuda_bf16.h>
#include <cstdint>

// dims: B=64, T=512, D=U=1024, 4U=4096
#define NCTA 64

// ---------------- scratch (__device__ globals) -----------------------------
__device__ __align__(16) __nv_bfloat16 g_xh[(size_t)32768 * 1024];
__device__ __align__(16) __nv_bfloat16 g_xl[(size_t)32768 * 1024];
__device__ __align__(16) __nv_bfloat16 g_wxh[(size_t)4096 * 1024];
__device__ __align__(16) __nv_bfloat16 g_wxl[(size_t)4096 * 1024];
__device__ __align__(16) __nv_bfloat16 g_whh[(size_t)4096 * 1024];
__device__ __align__(16) __nv_bfloat16 g_whl[(size_t)4096 * 1024];
// write-once h history: step t reads [t], writes [t+1]
__device__ __align__(16) __nv_bfloat16 g_hth[513][64 * 1024];
__device__ __align__(16) __nv_bfloat16 g_htl[513][64 * 1024];
__device__ float g_c[64 * 1024];                       // [b][u]
__device__ float g_xproj[(size_t)512 * 4096 * 64];     // [t][p][b], bias folded
__device__ int g_cnt[512];                              // per-step arrival counters

// ---------------- helpers --------------------------------------------------
__device__ __forceinline__ uint32_t smem_u32(const void* p) {
    uint32_t a;
    asm("{ .reg .u64 t; cvta.to.shared.u64 t, %1; cvt.u32.u64 %0, t; }" : "=r"(a) : "l"(p));
    return a;
}
__device__ __forceinline__ void cp16(uint32_t saddr, const void* g) {
    asm volatile("cp.async.cg.shared.global [%0], [%1], 16;" :: "r"(saddr), "l"(g) : "memory");
}
#define CP_COMMIT() asm volatile("cp.async.commit_group;" ::: "memory")
#define CP_WAIT1()  asm volatile("cp.async.wait_group 1;" ::: "memory")
#define CP_WAIT0()  asm volatile("cp.async.wait_group 0;" ::: "memory")

__device__ __forceinline__ void ldsm4(uint32_t* r, uint32_t addr) {
    asm volatile("ldmatrix.sync.aligned.m8n8.x4.shared.b16 {%0,%1,%2,%3}, [%4];"
        : "=r"(r[0]), "=r"(r[1]), "=r"(r[2]), "=r"(r[3]) : "r"(addr));
}
__device__ __forceinline__ void mma_bf16(float* c, const uint32_t* a, uint32_t b0, uint32_t b1) {
    asm volatile("mma.sync.aligned.m16n8k16.row.col.f32.bf16.bf16.f32 "
        "{%0,%1,%2,%3}, {%4,%5,%6,%7}, {%8,%9}, {%0,%1,%2,%3};"
        : "+f"(c[0]), "+f"(c[1]), "+f"(c[2]), "+f"(c[3])
        : "r"(a[0]), "r"(a[1]), "r"(a[2]), "r"(a[3]), "r"(b0), "r"(b1));
}
__device__ __forceinline__ void red_release(int* p) {
    asm volatile("red.release.gpu.global.add.s32 [%0], 1;" :: "l"(p) : "memory");
}
__device__ __forceinline__ int ld_acq(const int* p) {
    int v; asm volatile("ld.acquire.gpu.global.b32 %0, [%1];" : "=r"(v) : "l"(p) : "memory"); return v;
}
// column permutation: p = j*64 + g*16 + uu  <->  gcol = g*1024 + j*16 + uu
__device__ __forceinline__ int gcol_of(int p) {
    return ((p >> 4) & 3) * 1024 + (p >> 6) * 16 + (p & 15);
}
// smem tile: rows of 128B (64 bf16), 16B chunks xor-swizzled by row
__device__ __forceinline__ uint32_t tadr(int row, int ch) {
    return (uint32_t)(row * 128 + ((ch ^ (row & 7)) << 4));
}

// ---------------- init -----------------------------------------------------
__global__ void init_kernel() {
    int i = blockIdx.x * 256 + threadIdx.x;
    uint4 z = make_uint4(0, 0, 0, 0);
    if (i < 8192) { ((uint4*)g_hth[0])[i] = z; ((uint4*)g_htl[0])[i] = z; }
    if (i < 16384) ((uint4*)g_c)[i] = z;
    if (i < 512) g_cnt[i] = 0;
}

// ---------------- packers --------------------------------------------------
__global__ void __launch_bounds__(256) pack_x_kernel(const float* __restrict__ x) {
    int u = blockIdx.x * 256 + threadIdx.x;           // 4194304
    int k8 = u & 127, m = u >> 7;
    int t = m >> 6, b = m & 63;
    const float* s = x + ((size_t)(b * 512 + t)) * 1024 + k8 * 8;
    float4 v0 = *(const float4*)s, v1 = *(const float4*)(s + 4);
    float v[8] = {v0.x, v0.y, v0.z, v0.w, v1.x, v1.y, v1.z, v1.w};
    __nv_bfloat16 hb[8], lb[8];
#pragma unroll
    for (int i = 0; i < 8; i++) {
        hb[i] = __float2bfloat16(v[i]);
        lb[i] = __float2bfloat16(v[i] - __bfloat162float(hb[i]));
    }
    size_t o = (size_t)m * 1024 + k8 * 8;
    *(uint4*)(g_xh + o) = *(uint4*)hb;
    *(uint4*)(g_xl + o) = *(uint4*)lb;
}

__global__ void __launch_bounds__(256) pack_w_kernel(const float* __restrict__ W, int mode) {
    __shared__ float s[32][33];
    int p0 = blockIdx.x * 32, k0 = blockIdx.y * 32;
    int tid = threadIdx.x;
#pragma unroll
    for (int i = 0; i < 4; i++) {
        int idx = tid + i * 256;
        int kk = idx >> 5, pp = idx & 31;
        s[kk][pp] = W[(size_t)(k0 + kk) * 4096 + gcol_of(p0 + pp)];
    }
    __syncthreads();
    if (tid < 128) {
        int pp = tid >> 2, k8 = (tid & 3) * 8;
        __nv_bfloat16 hb[8], lb[8];
#pragma unroll
        for (int i = 0; i < 8; i++) {
            float v = s[k8 + i][pp];
            hb[i] = __float2bfloat16(v);
            lb[i] = __float2bfloat16(v - __bfloat162float(hb[i]));
        }
        size_t o = (size_t)(p0 + pp) * 1024 + k0 + k8;
        __nv_bfloat16* dh = mode ? g_whh : g_wxh;
        __nv_bfloat16* dl = mode ? g_whl : g_wxl;
        *(uint4*)(dh + o) = *(uint4*)hb;
        *(uint4*)(dl + o) = *(uint4*)lb;
    }
}

// ---------------- x_proj GEMM (R4 verbatim) --------------------------------
__device__ __forceinline__ void xp_load(uint32_t sb, int s, int tid, int m0, int p0, int k0) {
    uint32_t st = sb + s * 65536;
#pragma unroll
    for (int rep = 0; rep < 4; rep++) {
        int c = tid + rep * 256;
        int row = c >> 3, ch = c & 7;
        uint32_t so = tadr(row, ch);
        size_t go = (size_t)k0 + ch * 8;
        cp16(st + so,         g_xh  + (size_t)(m0 + row) * 1024 + go);
        cp16(st + 16384 + so, g_xl  + (size_t)(m0 + row) * 1024 + go);
        cp16(st + 32768 + so, g_wxh + (size_t)(p0 + row) * 1024 + go);
        cp16(st + 49152 + so, g_wxl + (size_t)(p0 + row) * 1024 + go);
    }
}

__device__ __forceinline__ void xp_compute(uint32_t sb, int s, int lane,
                                           int m_off, int n_off, float C[16][4]) {
    uint32_t st = sb + s * 65536;
    int r15 = lane & 15, kh = lane >> 4;
#pragma unroll
    for (int ks = 0; ks < 4; ks++) {
        int ch = ks * 2 + kh;
        uint32_t aH[8], aL[8], bH[16], bL[16];
#pragma unroll
        for (int mt = 0; mt < 2; mt++) {
            uint32_t o = tadr(m_off + mt * 16 + r15, ch);
            ldsm4(aH + mt * 4, st + o);
            ldsm4(aL + mt * 4, st + 16384 + o);
        }
#pragma unroll
        for (int nt = 0; nt < 4; nt++) {
            uint32_t o = tadr(n_off + nt * 16 + r15, ch);
            ldsm4(bH + nt * 4, st + 32768 + o);
            ldsm4(bL + nt * 4, st + 49152 + o);
        }
#pragma unroll
        for (int mt = 0; mt < 2; mt++)
#pragma unroll
            for (int n8 = 0; n8 < 8; n8++) {
                int g = (n8 >> 1) * 4 + (n8 & 1);
                float* cc = C[mt * 8 + n8];
                mma_bf16(cc, aH + mt * 4, bH[g], bH[g + 2]);
                mma_bf16(cc, aH + mt * 4, bL[g], bL[g + 2]);
                mma_bf16(cc, aL + mt * 4, bH[g], bH[g + 2]);
            }
    }
}

__global__ void __launch_bounds__(256, 1) xproj_kernel(const float* __restrict__ bias) {
    extern __shared__ __align__(16) unsigned char sm[];
    uint32_t sb = smem_u32(sm);
    int tid = threadIdx.x, lane = tid & 31, w = tid >> 5;
    int p0 = blockIdx.x * 128, m0 = blockIdx.y * 128;
    int m_off = (w & 3) * 32, n_off = (w >> 2) * 64;

    float C[16][4];
#pragma unroll
    for (int i = 0; i < 16; i++)
#pragma unroll
        for (int q = 0; q < 4; q++) C[i][q] = 0.0f;

    xp_load(sb, 0, tid, m0, p0, 0);  CP_COMMIT();
    xp_load(sb, 1, tid, m0, p0, 64); CP_COMMIT();
#pragma unroll 1
    for (int kt = 0; kt < 16; kt++) {
        if (kt < 15) { CP_WAIT1(); } else { CP_WAIT0(); }
        __syncthreads();
        xp_compute(sb, kt & 1, lane, m_off, n_off, C);
        __syncthreads();
        if (kt + 2 < 16) { xp_load(sb, kt & 1, tid, m0, p0, (kt + 2) * 64); CP_COMMIT(); }
    }

    float* sC = (float*)sm;  // [128][132]
    int r = lane >> 2, c2 = (lane & 3) * 2;
#pragma unroll
    for (int mt = 0; mt < 2; mt++)
#pragma unroll
        for (int n8 = 0; n8 < 8; n8++) {
            float* cf = C[mt * 8 + n8];
            int m = m_off + mt * 16 + r;
            int n = n_off + n8 * 8 + c2;
            sC[n * 132 + m]           = cf[0];
            sC[(n + 1) * 132 + m]     = cf[1];
            sC[n * 132 + m + 8]       = cf[2];
            sC[(n + 1) * 132 + m + 8] = cf[3];
        }
    __syncthreads();
    {
        int n = tid >> 1, tq = tid & 1;
        int p = p0 + n;
        float bv = bias[gcol_of(p)];
        float* dst = g_xproj + ((size_t)(blockIdx.y * 2 + tq) * 4096 + p) * 64;
        const float* src = sC + n * 132 + tq * 64;
#pragma unroll
        for (int i = 0; i < 16; i++) {
            float4 v = *(const float4*)(src + i * 4);
            v.x += bv; v.y += bv; v.z += bv; v.w += bv;
            *(float4*)(dst + i * 4) = v;
        }
    }
}

// ---------------- persistent recurrence (R4 step body verbatim) ------------
// smem: stages 2x32KB (Ah 8K, Al 8K, Bh 8K, Bl 8K) + Xp 16KB at 65536 = 81920
__device__ __forceinline__ void st_load(uint32_t sb, int s, int tid,
                                        const __nv_bfloat16* hh, const __nv_bfloat16* hl,
                                        int p0, int k0) {
    uint32_t st = sb + s * 32768;
#pragma unroll
    for (int rep = 0; rep < 2; rep++) {
        int c = tid + rep * 256;
        int row = c >> 3, ch = c & 7;
        uint32_t so = tadr(row, ch);
        size_t go = (size_t)k0 + ch * 8;
        cp16(st + so,         hh + (size_t)row * 1024 + go);
        cp16(st + 8192 + so,  hl + (size_t)row * 1024 + go);
        cp16(st + 16384 + so, g_whh + (size_t)(p0 + row) * 1024 + go);
        cp16(st + 24576 + so, g_whl + (size_t)(p0 + row) * 1024 + go);
    }
}

__device__ __forceinline__ void st_compute(uint32_t sb, int s, int lane,
                                           int m_off, int n_off, float C[4][4]) {
    uint32_t st = sb + s * 32768;
    int r15 = lane & 15, kh = lane >> 4;
#pragma unroll
    for (int ks = 0; ks < 4; ks++) {
        int ch = ks * 2 + kh;
        uint32_t aH[8], aL[8], bH[4], bL[4];
#pragma unroll
        for (int mt = 0; mt < 2; mt++) {
            uint32_t o = tadr(m_off + mt * 16 + r15, ch);
            ldsm4(aH + mt * 4, st + o);
            ldsm4(aL + mt * 4, st + 8192 + o);
        }
        {
            uint32_t o = tadr(n_off + r15, ch);
            ldsm4(bH, st + 16384 + o);
            ldsm4(bL, st + 24576 + o);
        }
#pragma unroll
        for (int mt = 0; mt < 2; mt++)
#pragma unroll
            for (int nn = 0; nn < 2; nn++) {
                float* cc = C[mt * 2 + nn];
                mma_bf16(cc, aH + mt * 4, bH[nn], bH[nn + 2]);
                mma_bf16(cc, aH + mt * 4, bL[nn], bL[nn + 2]);
                mma_bf16(cc, aL + mt * 4, bH[nn], bH[nn + 2]);
            }
    }
}

__global__ void __launch_bounds__(256, 1) step_persist(float* __restrict__ y) {
    extern __shared__ __align__(16) unsigned char sm[];
    uint32_t sb = smem_u32(sm);
    const int tid = threadIdx.x, lane = tid & 31, w = tid >> 5;
    const int j = blockIdx.x, p0 = j * 64;
    const int m_off = (w & 1) * 32, n_off = (w >> 1) * 16;

#pragma unroll 1
    for (int t = 0; t < 512; t++) {
        const __nv_bfloat16* hh = g_hth[t];
        const __nv_bfloat16* hl = g_htl[t];

        // x_proj slice (16KB) grouped with first stage (R4 verbatim)
        {
            const char* xpg = (const char*)(g_xproj + ((size_t)t * 4096 + p0) * 64);
#pragma unroll
            for (int rep = 0; rep < 4; rep++) {
                int c = tid + rep * 256;
                cp16(sb + 65536 + c * 16, xpg + c * 16);
            }
        }
        st_load(sb, 0, tid, hh, hl, p0, 0);  CP_COMMIT();
        st_load(sb, 1, tid, hh, hl, p0, 64); CP_COMMIT();

        float C[4][4];
#pragma unroll
        for (int i = 0; i < 4; i++)
#pragma unroll
            for (int q = 0; q < 4; q++) C[i][q] = 0.0f;

#pragma unroll 1
        for (int kt = 0; kt < 16; kt++) {
            if (kt < 15) { CP_WAIT1(); } else { CP_WAIT0(); }
            __syncthreads();
            st_compute(sb, kt & 1, lane, m_off, n_off, C);
            __syncthreads();
            if (kt + 2 < 16) { st_load(sb, kt & 1, tid, hh, hl, p0, (kt + 2) * 64); CP_COMMIT(); }
        }

        // frags -> Zs[n][b] (Zs overlays stage 0; all loads retired, synced)
        float* Zs = (float*)sm;                        // [64][66]
        const float* Xp = (const float*)(sm + 65536);  // [64 p][64 b]
        {
            int r = lane >> 2, c2 = (lane & 3) * 2;
#pragma unroll
            for (int mt = 0; mt < 2; mt++)
#pragma unroll
                for (int nn = 0; nn < 2; nn++) {
                    float* cf = C[mt * 2 + nn];
                    int m = m_off + mt * 16 + r;
                    int n = n_off + nn * 8 + c2;
                    Zs[n * 66 + m]           = cf[0];
                    Zs[(n + 1) * 66 + m]     = cf[1];
                    Zs[n * 66 + m + 8]       = cf[2];
                    Zs[(n + 1) * 66 + m + 8] = cf[3];
                }
        }
        __syncthreads();
        {
            int b = tid >> 2, uq = tid & 3;
            float hv[4];
#pragma unroll
            for (int v = 0; v < 4; v++) {
                int uu = uq * 4 + v, u = j * 16 + uu;
                float zi = Zs[uu * 66 + b]        + Xp[uu * 64 + b];
                float zf = Zs[(16 + uu) * 66 + b] + Xp[(16 + uu) * 64 + b];
                float zg = Zs[(32 + uu) * 66 + b] + Xp[(32 + uu) * 64 + b];
                float zo = Zs[(48 + uu) * 66 + b] + Xp[(48 + uu) * 64 + b];
                float ig = 1.0f / (1.0f + __expf(-zi));
                float fg = 1.0f / (1.0f + __expf(-zf));
                float gg = 2.0f / (1.0f + __expf(-2.0f * zg)) - 1.0f;
                float og = 1.0f / (1.0f + __expf(-zo));
                float cn = fg * g_c[b * 1024 + u] + ig * gg;
                g_c[b * 1024 + u] = cn;
                float th = 2.0f / (1.0f + __expf(-2.0f * cn)) - 1.0f;
                hv[v] = og * th;
                y[((size_t)b * 512 + t) * 1024 + u] = hv[v];
            }
            __nv_bfloat16 hb[4], lb[4];
#pragma unroll
            for (int v = 0; v < 4; v++) {
                hb[v] = __float2bfloat16(hv[v]);
                lb[v] = __float2bfloat16(hv[v] - __bfloat162float(hb[v]));
            }
            size_t o = (size_t)b * 1024 + j * 16 + uq * 4;
            *(uint2*)(g_hth[t + 1] + o) = *(uint2*)hb;
            *(uint2*)(g_htl[t + 1] + o) = *(uint2*)lb;
        }

        // ---- grid barrier: release arrival, acquire poll ------------------
        __threadfence();
        __syncthreads();
        if (tid == 0) {
            red_release(&g_cnt[t]);
            while (ld_acq(&g_cnt[t]) < NCTA) { }
            __threadfence();
        }
        __syncthreads();
    }
}

// ---------------------------------------------------------------------------
extern "C" void kernel_launch(void* const* d_in, const int* in_sizes, int n_in,
                              void* d_out, int out_size)
{
    const float* x  = (const float*)d_in[0];
    const float* Wx = (const float*)d_in[1];
    const float* Wh = (const float*)d_in[2];
    const float* b  = (const float*)d_in[3];
    float* y = (float*)d_out;

    cudaFuncSetAttribute(xproj_kernel, cudaFuncAttributeMaxDynamicSharedMemorySize, 131072);
    cudaFuncSetAttribute(step_persist, cudaFuncAttributeMaxDynamicSharedMemorySize, 81920);

    init_kernel<<<64, 256>>>();
    pack_x_kernel<<<16384, 256>>>(x);
    pack_w_kernel<<<dim3(128, 32), 256>>>(Wx, 0);
    pack_w_kernel<<<dim3(128, 32), 256>>>(Wh, 1);
    xproj_kernel<<<dim3(32, 256), 256, 131072>>>(b);
    step_persist<<<NCTA, 256, 81920>>>(y);
}

// round 9
// speedup vs baseline: 1.1868x; 1.1868x over previous
#include <cuda_runtime.h>
#include <cuda_bf16.h>
#include <cuda_fp16.h>
#include <cstdint>

// dims: B=64, T=512, D=U=1024, 4U=4096
#define NCTA 64

// ---------------- scratch (__device__ globals) -----------------------------
__device__ __align__(16) __nv_bfloat16 g_xh[(size_t)32768 * 1024];
__device__ __align__(16) __nv_bfloat16 g_xl[(size_t)32768 * 1024];
__device__ __align__(16) __nv_bfloat16 g_wxh[(size_t)4096 * 1024];
__device__ __align__(16) __nv_bfloat16 g_wxl[(size_t)4096 * 1024];
__device__ __align__(16) __half g_whfh[(size_t)4096 * 1024];   // Wh fp16 hi
__device__ __align__(16) __half g_whfl[(size_t)4096 * 1024];   // Wh fp16 lo
// write-once h history (fp16): step t reads [t], writes [t+1]
__device__ __align__(16) __half g_htf[513][64 * 1024];
__device__ float g_c[64 * 1024];                       // [b][u]
__device__ float g_xproj[(size_t)512 * 4096 * 64];     // [t][p][b], bias folded
__device__ int g_cnt[512];                              // per-step arrival counters

// ---------------- helpers --------------------------------------------------
__device__ __forceinline__ uint32_t smem_u32(const void* p) {
    uint32_t a;
    asm("{ .reg .u64 t; cvta.to.shared.u64 t, %1; cvt.u32.u64 %0, t; }" : "=r"(a) : "l"(p));
    return a;
}
__device__ __forceinline__ void cp16(uint32_t saddr, const void* g) {
    asm volatile("cp.async.cg.shared.global [%0], [%1], 16;" :: "r"(saddr), "l"(g) : "memory");
}
#define CP_COMMIT() asm volatile("cp.async.commit_group;" ::: "memory")
#define CP_WAIT1()  asm volatile("cp.async.wait_group 1;" ::: "memory")
#define CP_WAIT0()  asm volatile("cp.async.wait_group 0;" ::: "memory")

__device__ __forceinline__ void ldsm4(uint32_t* r, uint32_t addr) {
    asm volatile("ldmatrix.sync.aligned.m8n8.x4.shared.b16 {%0,%1,%2,%3}, [%4];"
        : "=r"(r[0]), "=r"(r[1]), "=r"(r[2]), "=r"(r[3]) : "r"(addr));
}
__device__ __forceinline__ void mma_bf16(float* c, const uint32_t* a, uint32_t b0, uint32_t b1) {
    asm volatile("mma.sync.aligned.m16n8k16.row.col.f32.bf16.bf16.f32 "
        "{%0,%1,%2,%3}, {%4,%5,%6,%7}, {%8,%9}, {%0,%1,%2,%3};"
        : "+f"(c[0]), "+f"(c[1]), "+f"(c[2]), "+f"(c[3])
        : "r"(a[0]), "r"(a[1]), "r"(a[2]), "r"(a[3]), "r"(b0), "r"(b1));
}
__device__ __forceinline__ void mma_f16(float* c, const uint32_t* a, uint32_t b0, uint32_t b1) {
    asm volatile("mma.sync.aligned.m16n8k16.row.col.f32.f16.f16.f32 "
        "{%0,%1,%2,%3}, {%4,%5,%6,%7}, {%8,%9}, {%0,%1,%2,%3};"
        : "+f"(c[0]), "+f"(c[1]), "+f"(c[2]), "+f"(c[3])
        : "r"(a[0]), "r"(a[1]), "r"(a[2]), "r"(a[3]), "r"(b0), "r"(b1));
}
__device__ __forceinline__ void red_release(int* p) {
    asm volatile("red.release.gpu.global.add.s32 [%0], 1;" :: "l"(p) : "memory");
}
__device__ __forceinline__ int ld_acq(const int* p) {
    int v; asm volatile("ld.acquire.gpu.global.b32 %0, [%1];" : "=r"(v) : "l"(p) : "memory"); return v;
}
// column permutation: p = j*64 + g*16 + uu  <->  gcol = g*1024 + j*16 + uu
__device__ __forceinline__ int gcol_of(int p) {
    return ((p >> 4) & 3) * 1024 + (p >> 6) * 16 + (p & 15);
}
// smem tile: rows of 128B (64 bf16/fp16), 16B chunks xor-swizzled by row
__device__ __forceinline__ uint32_t tadr(int row, int ch) {
    return (uint32_t)(row * 128 + ((ch ^ (row & 7)) << 4));
}

// ---------------- init -----------------------------------------------------
__global__ void init_kernel() {
    int i = blockIdx.x * 256 + threadIdx.x;
    uint4 z = make_uint4(0, 0, 0, 0);
    if (i < 8192) ((uint4*)g_htf[0])[i] = z;
    if (i < 16384) ((uint4*)g_c)[i] = z;
    if (i < 512) g_cnt[i] = 0;
}

// ---------------- packers --------------------------------------------------
__global__ void __launch_bounds__(256) pack_x_kernel(const float* __restrict__ x) {
    int u = blockIdx.x * 256 + threadIdx.x;           // 4194304
    int k8 = u & 127, m = u >> 7;
    int t = m >> 6, b = m & 63;
    const float* s = x + ((size_t)(b * 512 + t)) * 1024 + k8 * 8;
    float4 v0 = *(const float4*)s, v1 = *(const float4*)(s + 4);
    float v[8] = {v0.x, v0.y, v0.z, v0.w, v1.x, v1.y, v1.z, v1.w};
    __nv_bfloat16 hb[8], lb[8];
#pragma unroll
    for (int i = 0; i < 8; i++) {
        hb[i] = __float2bfloat16(v[i]);
        lb[i] = __float2bfloat16(v[i] - __bfloat162float(hb[i]));
    }
    size_t o = (size_t)m * 1024 + k8 * 8;
    *(uint4*)(g_xh + o) = *(uint4*)hb;
    *(uint4*)(g_xl + o) = *(uint4*)lb;
}

__global__ void __launch_bounds__(256) pack_w_kernel(const float* __restrict__ W, int mode) {
    __shared__ float s[32][33];
    int p0 = blockIdx.x * 32, k0 = blockIdx.y * 32;
    int tid = threadIdx.x;
#pragma unroll
    for (int i = 0; i < 4; i++) {
        int idx = tid + i * 256;
        int kk = idx >> 5, pp = idx & 31;
        s[kk][pp] = W[(size_t)(k0 + kk) * 4096 + gcol_of(p0 + pp)];
    }
    __syncthreads();
    if (tid < 128) {
        int pp = tid >> 2, k8 = (tid & 3) * 8;
        size_t o = (size_t)(p0 + pp) * 1024 + k0 + k8;
        if (mode) {
            // Wh -> fp16 hi/lo
            __half hb[8], lb[8];
#pragma unroll
            for (int i = 0; i < 8; i++) {
                float v = s[k8 + i][pp];
                hb[i] = __float2half_rn(v);
                lb[i] = __float2half_rn(v - __half2float(hb[i]));
            }
            *(uint4*)(g_whfh + o) = *(uint4*)hb;
            *(uint4*)(g_whfl + o) = *(uint4*)lb;
        } else {
            // Wx -> bf16 hi/lo
            __nv_bfloat16 hb[8], lb[8];
#pragma unroll
            for (int i = 0; i < 8; i++) {
                float v = s[k8 + i][pp];
                hb[i] = __float2bfloat16(v);
                lb[i] = __float2bfloat16(v - __bfloat162float(hb[i]));
            }
            *(uint4*)(g_wxh + o) = *(uint4*)hb;
            *(uint4*)(g_wxl + o) = *(uint4*)lb;
        }
    }
}

// ---------------- x_proj GEMM (R4 verbatim, bf16 3-pass) -------------------
__device__ __forceinline__ void xp_load(uint32_t sb, int s, int tid, int m0, int p0, int k0) {
    uint32_t st = sb + s * 65536;
#pragma unroll
    for (int rep = 0; rep < 4; rep++) {
        int c = tid + rep * 256;
        int row = c >> 3, ch = c & 7;
        uint32_t so = tadr(row, ch);
        size_t go = (size_t)k0 + ch * 8;
        cp16(st + so,         g_xh  + (size_t)(m0 + row) * 1024 + go);
        cp16(st + 16384 + so, g_xl  + (size_t)(m0 + row) * 1024 + go);
        cp16(st + 32768 + so, g_wxh + (size_t)(p0 + row) * 1024 + go);
        cp16(st + 49152 + so, g_wxl + (size_t)(p0 + row) * 1024 + go);
    }
}

__device__ __forceinline__ void xp_compute(uint32_t sb, int s, int lane,
                                           int m_off, int n_off, float C[16][4]) {
    uint32_t st = sb + s * 65536;
    int r15 = lane & 15, kh = lane >> 4;
#pragma unroll
    for (int ks = 0; ks < 4; ks++) {
        int ch = ks * 2 + kh;
        uint32_t aH[8], aL[8], bH[16], bL[16];
#pragma unroll
        for (int mt = 0; mt < 2; mt++) {
            uint32_t o = tadr(m_off + mt * 16 + r15, ch);
            ldsm4(aH + mt * 4, st + o);
            ldsm4(aL + mt * 4, st + 16384 + o);
        }
#pragma unroll
        for (int nt = 0; nt < 4; nt++) {
            uint32_t o = tadr(n_off + nt * 16 + r15, ch);
            ldsm4(bH + nt * 4, st + 32768 + o);
            ldsm4(bL + nt * 4, st + 49152 + o);
        }
#pragma unroll
        for (int mt = 0; mt < 2; mt++)
#pragma unroll
            for (int n8 = 0; n8 < 8; n8++) {
                int g = (n8 >> 1) * 4 + (n8 & 1);
                float* cc = C[mt * 8 + n8];
                mma_bf16(cc, aH + mt * 4, bH[g], bH[g + 2]);
                mma_bf16(cc, aH + mt * 4, bL[g], bL[g + 2]);
                mma_bf16(cc, aL + mt * 4, bH[g], bH[g + 2]);
            }
    }
}

__global__ void __launch_bounds__(256, 1) xproj_kernel(const float* __restrict__ bias) {
    extern __shared__ __align__(16) unsigned char sm[];
    uint32_t sb = smem_u32(sm);
    int tid = threadIdx.x, lane = tid & 31, w = tid >> 5;
    int p0 = blockIdx.x * 128, m0 = blockIdx.y * 128;
    int m_off = (w & 3) * 32, n_off = (w >> 2) * 64;

    float C[16][4];
#pragma unroll
    for (int i = 0; i < 16; i++)
#pragma unroll
        for (int q = 0; q < 4; q++) C[i][q] = 0.0f;

    xp_load(sb, 0, tid, m0, p0, 0);  CP_COMMIT();
    xp_load(sb, 1, tid, m0, p0, 64); CP_COMMIT();
#pragma unroll 1
    for (int kt = 0; kt < 16; kt++) {
        if (kt < 15) { CP_WAIT1(); } else { CP_WAIT0(); }
        __syncthreads();
        xp_compute(sb, kt & 1, lane, m_off, n_off, C);
        __syncthreads();
        if (kt + 2 < 16) { xp_load(sb, kt & 1, tid, m0, p0, (kt + 2) * 64); CP_COMMIT(); }
    }

    float* sC = (float*)sm;  // [128][132]
    int r = lane >> 2, c2 = (lane & 3) * 2;
#pragma unroll
    for (int mt = 0; mt < 2; mt++)
#pragma unroll
        for (int n8 = 0; n8 < 8; n8++) {
            float* cf = C[mt * 8 + n8];
            int m = m_off + mt * 16 + r;
            int n = n_off + n8 * 8 + c2;
            sC[n * 132 + m]           = cf[0];
            sC[(n + 1) * 132 + m]     = cf[1];
            sC[n * 132 + m + 8]       = cf[2];
            sC[(n + 1) * 132 + m + 8] = cf[3];
        }
    __syncthreads();
    {
        int n = tid >> 1, tq = tid & 1;
        int p = p0 + n;
        float bv = bias[gcol_of(p)];
        float* dst = g_xproj + ((size_t)(blockIdx.y * 2 + tq) * 4096 + p) * 64;
        const float* src = sC + n * 132 + tq * 64;
#pragma unroll
        for (int i = 0; i < 16; i++) {
            float4 v = *(const float4*)(src + i * 4);
            v.x += bv; v.y += bv; v.z += bv; v.w += bv;
            *(float4*)(dst + i * 4) = v;
        }
    }
}

// ---------------- persistent recurrence (fp16 2-pass) ----------------------
// stage (24KB): A_h16 8K | WhHi 8K | WhLo 8K; 2 stages; Xp 16KB at 49152.
#define STG 24576
#define XP_OFF 49152
#define ST_SMEM 65536

__device__ __forceinline__ void st_load(uint32_t sb, int s, int tid,
                                        const __half* hf, int p0, int k0) {
    uint32_t st = sb + s * STG;
#pragma unroll
    for (int rep = 0; rep < 2; rep++) {
        int c = tid + rep * 256;
        int row = c >> 3, ch = c & 7;
        uint32_t so = tadr(row, ch);
        size_t go = (size_t)k0 + ch * 8;
        cp16(st + so,         hf + (size_t)row * 1024 + go);
        cp16(st + 8192 + so,  g_whfh + (size_t)(p0 + row) * 1024 + go);
        cp16(st + 16384 + so, g_whfl + (size_t)(p0 + row) * 1024 + go);
    }
}

__device__ __forceinline__ void st_compute(uint32_t sb, int s, int lane,
                                           int m_off, int n_off, float C[4][4]) {
    uint32_t st = sb + s * STG;
    int r15 = lane & 15, kh = lane >> 4;
#pragma unroll
    for (int ks = 0; ks < 4; ks++) {
        int ch = ks * 2 + kh;
        uint32_t aH[8], bH[4], bL[4];
#pragma unroll
        for (int mt = 0; mt < 2; mt++) {
            uint32_t o = tadr(m_off + mt * 16 + r15, ch);
            ldsm4(aH + mt * 4, st + o);
        }
        {
            uint32_t o = tadr(n_off + r15, ch);
            ldsm4(bH, st + 8192 + o);
            ldsm4(bL, st + 16384 + o);
        }
#pragma unroll
        for (int mt = 0; mt < 2; mt++)
#pragma unroll
            for (int nn = 0; nn < 2; nn++) {
                float* cc = C[mt * 2 + nn];
                mma_f16(cc, aH + mt * 4, bH[nn], bH[nn + 2]);
                mma_f16(cc, aH + mt * 4, bL[nn], bL[nn + 2]);
            }
    }
}

__global__ void __launch_bounds__(256, 1) step_persist(float* __restrict__ y) {
    extern __shared__ __align__(16) unsigned char sm[];
    uint32_t sb = smem_u32(sm);
    const int tid = threadIdx.x, lane = tid & 31, w = tid >> 5;
    const int j = blockIdx.x, p0 = j * 64;
    const int m_off = (w & 1) * 32, n_off = (w >> 1) * 16;

#pragma unroll 1
    for (int t = 0; t < 512; t++) {
        const __half* hf = g_htf[t];

        // x_proj slice (16KB) grouped into first commit group
        {
            const char* xpg = (const char*)(g_xproj + ((size_t)t * 4096 + p0) * 64);
#pragma unroll
            for (int rep = 0; rep < 4; rep++) {
                int c = tid + rep * 256;
                cp16(sb + XP_OFF + c * 16, xpg + c * 16);
            }
        }
        st_load(sb, 0, tid, hf, p0, 0);  CP_COMMIT();
        st_load(sb, 1, tid, hf, p0, 64); CP_COMMIT();

        float C[4][4];
#pragma unroll
        for (int i = 0; i < 4; i++)
#pragma unroll
            for (int q = 0; q < 4; q++) C[i][q] = 0.0f;

#pragma unroll 1
        for (int kt = 0; kt < 16; kt++) {
            if (kt < 15) { CP_WAIT1(); } else { CP_WAIT0(); }
            __syncthreads();
            st_compute(sb, kt & 1, lane, m_off, n_off, C);
            __syncthreads();
            if (kt + 2 < 16) { st_load(sb, kt & 1, tid, hf, p0, (kt + 2) * 64); CP_COMMIT(); }
        }

        // frags -> Zs[n][b] (Zs overlays stage 0; all loads retired, synced)
        float* Zs = (float*)sm;                        // [64][66]
        const float* Xp = (const float*)(sm + XP_OFF); // [64 p][64 b]
        {
            int r = lane >> 2, c2 = (lane & 3) * 2;
#pragma unroll
            for (int mt = 0; mt < 2; mt++)
#pragma unroll
                for (int nn = 0; nn < 2; nn++) {
                    float* cf = C[mt * 2 + nn];
                    int m = m_off + mt * 16 + r;
                    int n = n_off + nn * 8 + c2;
                    Zs[n * 66 + m]           = cf[0];
                    Zs[(n + 1) * 66 + m]     = cf[1];
                    Zs[n * 66 + m + 8]       = cf[2];
                    Zs[(n + 1) * 66 + m + 8] = cf[3];
                }
        }
        __syncthreads();
        {
            int b = tid >> 2, uq = tid & 3;
            float hv[4];
#pragma unroll
            for (int v = 0; v < 4; v++) {
                int uu = uq * 4 + v, u = j * 16 + uu;
                float zi = Zs[uu * 66 + b]        + Xp[uu * 64 + b];
                float zf = Zs[(16 + uu) * 66 + b] + Xp[(16 + uu) * 64 + b];
                float zg = Zs[(32 + uu) * 66 + b] + Xp[(32 + uu) * 64 + b];
                float zo = Zs[(48 + uu) * 66 + b] + Xp[(48 + uu) * 64 + b];
                float ig = 1.0f / (1.0f + __expf(-zi));
                float fg = 1.0f / (1.0f + __expf(-zf));
                float gg = 2.0f / (1.0f + __expf(-2.0f * zg)) - 1.0f;
                float og = 1.0f / (1.0f + __expf(-zo));
                float cn = fg * g_c[b * 1024 + u] + ig * gg;
                g_c[b * 1024 + u] = cn;
                float th = 2.0f / (1.0f + __expf(-2.0f * cn)) - 1.0f;
                hv[v] = og * th;
                y[((size_t)b * 512 + t) * 1024 + u] = hv[v];
            }
            __half hf4[4];
#pragma unroll
            for (int v = 0; v < 4; v++) hf4[v] = __float2half_rn(hv[v]);
            *(uint2*)(g_htf[t + 1] + (size_t)b * 1024 + j * 16 + uq * 4) = *(uint2*)hf4;
        }

        // ---- grid barrier: release arrival, acquire poll ------------------
        __threadfence();
        __syncthreads();
        if (tid == 0) {
            red_release(&g_cnt[t]);
            while (ld_acq(&g_cnt[t]) < NCTA) { }
            __threadfence();
        }
        __syncthreads();
    }
}

// ---------------------------------------------------------------------------
extern "C" void kernel_launch(void* const* d_in, const int* in_sizes, int n_in,
                              void* d_out, int out_size)
{
    const float* x  = (const float*)d_in[0];
    const float* Wx = (const float*)d_in[1];
    const float* Wh = (const float*)d_in[2];
    const float* b  = (const float*)d_in[3];
    float* y = (float*)d_out;

    cudaFuncSetAttribute(xproj_kernel, cudaFuncAttributeMaxDynamicSharedMemorySize, 131072);
    cudaFuncSetAttribute(step_persist, cudaFuncAttributeMaxDynamicSharedMemorySize, ST_SMEM);

    init_kernel<<<64, 256>>>();
    pack_x_kernel<<<16384, 256>>>(x);
    pack_w_kernel<<<dim3(128, 32), 256>>>(Wx, 0);
    pack_w_kernel<<<dim3(128, 32), 256>>>(Wh, 1);
    xproj_kernel<<<dim3(32, 256), 256, 131072>>>(b);
    step_persist<<<NCTA, 256, ST_SMEM>>>(y);
}

// round 10
// speedup vs baseline: 1.7202x; 1.4494x over previous
#include <cuda_runtime.h>
#include <cuda_bf16.h>
#include <cuda_fp16.h>
#include <cstdint>

// dims: B=64, T=512, D=U=1024, 4U=4096
#define NCTA 128

// ---------------- scratch (__device__ globals) -----------------------------
__device__ __align__(16) __nv_bfloat16 g_xh[(size_t)32768 * 1024];
__device__ __align__(16) __nv_bfloat16 g_xl[(size_t)32768 * 1024];
__device__ __align__(16) __nv_bfloat16 g_wxh[(size_t)4096 * 1024];
__device__ __align__(16) __nv_bfloat16 g_wxl[(size_t)4096 * 1024];
__device__ __align__(16) __half g_whfh[(size_t)4096 * 1024];   // Wh fp16 (single)
// write-once h history (fp16): step t reads [t], writes [t+1]
__device__ __align__(16) __half g_htf[513][64 * 1024];
__device__ float g_c[64 * 1024];                       // [b][u]
__device__ float g_xproj[(size_t)512 * 4096 * 64];     // [t][p][b], bias folded
__device__ int g_cnt[512];                              // per-step arrival counters

// ---------------- helpers --------------------------------------------------
__device__ __forceinline__ uint32_t smem_u32(const void* p) {
    uint32_t a;
    asm("{ .reg .u64 t; cvta.to.shared.u64 t, %1; cvt.u32.u64 %0, t; }" : "=r"(a) : "l"(p));
    return a;
}
__device__ __forceinline__ void cp16(uint32_t saddr, const void* g) {
    asm volatile("cp.async.cg.shared.global [%0], [%1], 16;" :: "r"(saddr), "l"(g) : "memory");
}
#define CP_COMMIT() asm volatile("cp.async.commit_group;" ::: "memory")
#define CP_WAIT1()  asm volatile("cp.async.wait_group 1;" ::: "memory")
#define CP_WAIT0()  asm volatile("cp.async.wait_group 0;" ::: "memory")

__device__ __forceinline__ void ldsm4(uint32_t* r, uint32_t addr) {
    asm volatile("ldmatrix.sync.aligned.m8n8.x4.shared.b16 {%0,%1,%2,%3}, [%4];"
        : "=r"(r[0]), "=r"(r[1]), "=r"(r[2]), "=r"(r[3]) : "r"(addr));
}
__device__ __forceinline__ void ldsm2(uint32_t* r, uint32_t addr) {
    asm volatile("ldmatrix.sync.aligned.m8n8.x2.shared.b16 {%0,%1}, [%2];"
        : "=r"(r[0]), "=r"(r[1]) : "r"(addr));
}
__device__ __forceinline__ void mma_bf16(float* c, const uint32_t* a, uint32_t b0, uint32_t b1) {
    asm volatile("mma.sync.aligned.m16n8k16.row.col.f32.bf16.bf16.f32 "
        "{%0,%1,%2,%3}, {%4,%5,%6,%7}, {%8,%9}, {%0,%1,%2,%3};"
        : "+f"(c[0]), "+f"(c[1]), "+f"(c[2]), "+f"(c[3])
        : "r"(a[0]), "r"(a[1]), "r"(a[2]), "r"(a[3]), "r"(b0), "r"(b1));
}
__device__ __forceinline__ void mma_f16(float* c, const uint32_t* a, uint32_t b0, uint32_t b1) {
    asm volatile("mma.sync.aligned.m16n8k16.row.col.f32.f16.f16.f32 "
        "{%0,%1,%2,%3}, {%4,%5,%6,%7}, {%8,%9}, {%0,%1,%2,%3};"
        : "+f"(c[0]), "+f"(c[1]), "+f"(c[2]), "+f"(c[3])
        : "r"(a[0]), "r"(a[1]), "r"(a[2]), "r"(a[3]), "r"(b0), "r"(b1));
}
__device__ __forceinline__ void red_release(int* p) {
    asm volatile("red.release.gpu.global.add.s32 [%0], 1;" :: "l"(p) : "memory");
}
__device__ __forceinline__ int ld_acq(const int* p) {
    int v; asm volatile("ld.acquire.gpu.global.b32 %0, [%1];" : "=r"(v) : "l"(p) : "memory"); return v;
}
// column permutation: p = j*32 + g*8 + uu  <->  gcol = g*1024 + j*8 + uu
__device__ __forceinline__ int gcol_of(int p) {
    return ((p >> 3) & 3) * 1024 + (p >> 5) * 8 + (p & 7);
}
// smem tile: rows of 128B (64 bf16/fp16), 16B chunks xor-swizzled by row
__device__ __forceinline__ uint32_t tadr(int row, int ch) {
    return (uint32_t)(row * 128 + ((ch ^ (row & 7)) << 4));
}

// ---------------- init -----------------------------------------------------
__global__ void init_kernel() {
    int i = blockIdx.x * 256 + threadIdx.x;
    uint4 z = make_uint4(0, 0, 0, 0);
    if (i < 8192) ((uint4*)g_htf[0])[i] = z;
    if (i < 16384) ((uint4*)g_c)[i] = z;
    if (i < 512) g_cnt[i] = 0;
}

// ---------------- packers --------------------------------------------------
__global__ void __launch_bounds__(256) pack_x_kernel(const float* __restrict__ x) {
    int u = blockIdx.x * 256 + threadIdx.x;           // 4194304
    int k8 = u & 127, m = u >> 7;
    int t = m >> 6, b = m & 63;
    const float* s = x + ((size_t)(b * 512 + t)) * 1024 + k8 * 8;
    float4 v0 = *(const float4*)s, v1 = *(const float4*)(s + 4);
    float v[8] = {v0.x, v0.y, v0.z, v0.w, v1.x, v1.y, v1.z, v1.w};
    __nv_bfloat16 hb[8], lb[8];
#pragma unroll
    for (int i = 0; i < 8; i++) {
        hb[i] = __float2bfloat16(v[i]);
        lb[i] = __float2bfloat16(v[i] - __bfloat162float(hb[i]));
    }
    size_t o = (size_t)m * 1024 + k8 * 8;
    *(uint4*)(g_xh + o) = *(uint4*)hb;
    *(uint4*)(g_xl + o) = *(uint4*)lb;
}

__global__ void __launch_bounds__(256) pack_w_kernel(const float* __restrict__ W, int mode) {
    __shared__ float s[32][33];
    int p0 = blockIdx.x * 32, k0 = blockIdx.y * 32;
    int tid = threadIdx.x;
#pragma unroll
    for (int i = 0; i < 4; i++) {
        int idx = tid + i * 256;
        int kk = idx >> 5, pp = idx & 31;
        s[kk][pp] = W[(size_t)(k0 + kk) * 4096 + gcol_of(p0 + pp)];
    }
    __syncthreads();
    if (tid < 128) {
        int pp = tid >> 2, k8 = (tid & 3) * 8;
        size_t o = (size_t)(p0 + pp) * 1024 + k0 + k8;
        if (mode) {
            __half hb[8];
#pragma unroll
            for (int i = 0; i < 8; i++) hb[i] = __float2half_rn(s[k8 + i][pp]);
            *(uint4*)(g_whfh + o) = *(uint4*)hb;
        } else {
            __nv_bfloat16 hb[8], lb[8];
#pragma unroll
            for (int i = 0; i < 8; i++) {
                float v = s[k8 + i][pp];
                hb[i] = __float2bfloat16(v);
                lb[i] = __float2bfloat16(v - __bfloat162float(hb[i]));
            }
            *(uint4*)(g_wxh + o) = *(uint4*)hb;
            *(uint4*)(g_wxl + o) = *(uint4*)lb;
        }
    }
}

// ---------------- x_proj GEMM (proven bf16 3-pass) -------------------------
__device__ __forceinline__ void xp_load(uint32_t sb, int s, int tid, int m0, int p0, int k0) {
    uint32_t st = sb + s * 65536;
#pragma unroll
    for (int rep = 0; rep < 4; rep++) {
        int c = tid + rep * 256;
        int row = c >> 3, ch = c & 7;
        uint32_t so = tadr(row, ch);
        size_t go = (size_t)k0 + ch * 8;
        cp16(st + so,         g_xh  + (size_t)(m0 + row) * 1024 + go);
        cp16(st + 16384 + so, g_xl  + (size_t)(m0 + row) * 1024 + go);
        cp16(st + 32768 + so, g_wxh + (size_t)(p0 + row) * 1024 + go);
        cp16(st + 49152 + so, g_wxl + (size_t)(p0 + row) * 1024 + go);
    }
}

__device__ __forceinline__ void xp_compute(uint32_t sb, int s, int lane,
                                           int m_off, int n_off, float C[16][4]) {
    uint32_t st = sb + s * 65536;
    int r15 = lane & 15, kh = lane >> 4;
#pragma unroll
    for (int ks = 0; ks < 4; ks++) {
        int ch = ks * 2 + kh;
        uint32_t aH[8], aL[8], bH[16], bL[16];
#pragma unroll
        for (int mt = 0; mt < 2; mt++) {
            uint32_t o = tadr(m_off + mt * 16 + r15, ch);
            ldsm4(aH + mt * 4, st + o);
            ldsm4(aL + mt * 4, st + 16384 + o);
        }
#pragma unroll
        for (int nt = 0; nt < 4; nt++) {
            uint32_t o = tadr(n_off + nt * 16 + r15, ch);
            ldsm4(bH + nt * 4, st + 32768 + o);
            ldsm4(bL + nt * 4, st + 49152 + o);
        }
#pragma unroll
        for (int mt = 0; mt < 2; mt++)
#pragma unroll
            for (int n8 = 0; n8 < 8; n8++) {
                int g = (n8 >> 1) * 4 + (n8 & 1);
                float* cc = C[mt * 8 + n8];
                mma_bf16(cc, aH + mt * 4, bH[g], bH[g + 2]);
                mma_bf16(cc, aH + mt * 4, bL[g], bL[g + 2]);
                mma_bf16(cc, aL + mt * 4, bH[g], bH[g + 2]);
            }
    }
}

__global__ void __launch_bounds__(256, 1) xproj_kernel(const float* __restrict__ bias) {
    extern __shared__ __align__(16) unsigned char sm[];
    uint32_t sb = smem_u32(sm);
    int tid = threadIdx.x, lane = tid & 31, w = tid >> 5;
    int p0 = blockIdx.x * 128, m0 = blockIdx.y * 128;
    int m_off = (w & 3) * 32, n_off = (w >> 2) * 64;

    float C[16][4];
#pragma unroll
    for (int i = 0; i < 16; i++)
#pragma unroll
        for (int q = 0; q < 4; q++) C[i][q] = 0.0f;

    xp_load(sb, 0, tid, m0, p0, 0);  CP_COMMIT();
    xp_load(sb, 1, tid, m0, p0, 64); CP_COMMIT();
#pragma unroll 1
    for (int kt = 0; kt < 16; kt++) {
        if (kt < 15) { CP_WAIT1(); } else { CP_WAIT0(); }
        __syncthreads();
        xp_compute(sb, kt & 1, lane, m_off, n_off, C);
        __syncthreads();
        if (kt + 2 < 16) { xp_load(sb, kt & 1, tid, m0, p0, (kt + 2) * 64); CP_COMMIT(); }
    }

    float* sC = (float*)sm;  // [128][132]
    int r = lane >> 2, c2 = (lane & 3) * 2;
#pragma unroll
    for (int mt = 0; mt < 2; mt++)
#pragma unroll
        for (int n8 = 0; n8 < 8; n8++) {
            float* cf = C[mt * 8 + n8];
            int m = m_off + mt * 16 + r;
            int n = n_off + n8 * 8 + c2;
            sC[n * 132 + m]           = cf[0];
            sC[(n + 1) * 132 + m]     = cf[1];
            sC[n * 132 + m + 8]       = cf[2];
            sC[(n + 1) * 132 + m + 8] = cf[3];
        }
    __syncthreads();
    {
        int n = tid >> 1, tq = tid & 1;
        int p = p0 + n;
        float bv = bias[gcol_of(p)];
        float* dst = g_xproj + ((size_t)(blockIdx.y * 2 + tq) * 4096 + p) * 64;
        const float* src = sC + n * 132 + tq * 64;
#pragma unroll
        for (int i = 0; i < 16; i++) {
            float4 v = *(const float4*)(src + i * 4);
            v.x += bv; v.y += bv; v.z += bv; v.w += bv;
            *(float4*)(dst + i * 4) = v;
        }
    }
}

// ---------------- persistent recurrence (fp16 1-pass, 128 CTAs) ------------
// stage (24KB): A 2x8KB | Wh 2x4KB ; 2 stages = 48KB; Xp 8KB at 49152.
#define STG 24576
#define XP_OFF 49152
#define ST_SMEM 57344

__device__ __forceinline__ void st_load(uint32_t sb, int s, int tid,
                                        const __half* hf, int p0, int k0) {
    uint32_t st = sb + s * STG;
#pragma unroll
    for (int rep = 0; rep < 4; rep++) {          // A: 64 rows x 128 k
        int idx = tid + rep * 256;
        int c = idx >> 9, r = idx & 511;
        int row = r >> 3, ch = r & 7;
        cp16(st + c * 8192 + tadr(row, ch),
             hf + (size_t)row * 1024 + k0 + c * 64 + ch * 8);
    }
#pragma unroll
    for (int rep = 0; rep < 2; rep++) {          // B: 32 rows x 128 k
        int idx = tid + rep * 256;
        int c = idx >> 8, r = idx & 255;
        int row = r >> 3, ch = r & 7;
        cp16(st + 16384 + c * 4096 + tadr(row, ch),
             g_whfh + (size_t)(p0 + row) * 1024 + k0 + c * 64 + ch * 8);
    }
}

__device__ __forceinline__ void st_compute(uint32_t sb, int s, int lane,
                                           int m_off, int n_off, float C[2][4]) {
    uint32_t st = sb + s * STG;
    int r15 = lane & 15, kh = lane >> 4;
#pragma unroll
    for (int sub = 0; sub < 2; sub++) {
        uint32_t Ab = st + sub * 8192;
        uint32_t Bb = st + 16384 + sub * 4096;
#pragma unroll
        for (int ks = 0; ks < 4; ks++) {
            int ch = ks * 2 + kh;
            uint32_t aH[8], bH[2];
#pragma unroll
            for (int mt = 0; mt < 2; mt++)
                ldsm4(aH + mt * 4, Ab + tadr(m_off + mt * 16 + r15, ch));
            ldsm2(bH, Bb + tadr(n_off + (r15 & 7), ks * 2 + (r15 >> 3)));
#pragma unroll
            for (int mt = 0; mt < 2; mt++)
                mma_f16(C[mt], aH + mt * 4, bH[0], bH[1]);
        }
    }
}

__global__ void __launch_bounds__(256, 1) step_persist(float* __restrict__ y) {
    extern __shared__ __align__(16) unsigned char sm[];
    uint32_t sb = smem_u32(sm);
    const int tid = threadIdx.x, lane = tid & 31, w = tid >> 5;
    const int j = blockIdx.x, p0 = j * 32;
    const int m_off = (w & 1) * 32, n_off = (w >> 1) * 8;

#pragma unroll 1
    for (int t = 0; t < 512; t++) {
        const __half* hf = g_htf[t];

        // x_proj slice (8KB) grouped into first commit group
        {
            const char* xpg = (const char*)(g_xproj + ((size_t)t * 4096 + p0) * 64);
#pragma unroll
            for (int rep = 0; rep < 2; rep++) {
                int c = tid + rep * 256;
                cp16(sb + XP_OFF + c * 16, xpg + c * 16);
            }
        }
        st_load(sb, 0, tid, hf, p0, 0);   CP_COMMIT();
        st_load(sb, 1, tid, hf, p0, 128); CP_COMMIT();

        float C[2][4];
#pragma unroll
        for (int i = 0; i < 2; i++)
#pragma unroll
            for (int q = 0; q < 4; q++) C[i][q] = 0.0f;

#pragma unroll 1
        for (int kt = 0; kt < 8; kt++) {
            if (kt < 7) { CP_WAIT1(); } else { CP_WAIT0(); }
            __syncthreads();
            st_compute(sb, kt & 1, lane, m_off, n_off, C);
            __syncthreads();
            if (kt + 2 < 8) { st_load(sb, kt & 1, tid, hf, p0, (kt + 2) * 128); CP_COMMIT(); }
        }

        // frags -> Zs[n][b] (Zs overlays stage 0; all loads retired, synced)
        float* Zs = (float*)sm;                        // [32][66]
        const float* Xp = (const float*)(sm + XP_OFF); // [32 p][64 b]
        {
            int r = lane >> 2, c2 = (lane & 3) * 2;
#pragma unroll
            for (int mt = 0; mt < 2; mt++) {
                float* cf = C[mt];
                int m = m_off + mt * 16 + r;
                int n = n_off + c2;
                Zs[n * 66 + m]           = cf[0];
                Zs[(n + 1) * 66 + m]     = cf[1];
                Zs[n * 66 + m + 8]       = cf[2];
                Zs[(n + 1) * 66 + m + 8] = cf[3];
            }
        }
        __syncthreads();
        {
            int b = tid >> 2, uq = tid & 3;
            float hv[2];
#pragma unroll
            for (int v = 0; v < 2; v++) {
                int uu = uq * 2 + v, u = j * 8 + uu;
                float zi = Zs[uu * 66 + b]        + Xp[uu * 64 + b];
                float zf = Zs[(8 + uu) * 66 + b]  + Xp[(8 + uu) * 64 + b];
                float zg = Zs[(16 + uu) * 66 + b] + Xp[(16 + uu) * 64 + b];
                float zo = Zs[(24 + uu) * 66 + b] + Xp[(24 + uu) * 64 + b];
                float ig = 1.0f / (1.0f + __expf(-zi));
                float fg = 1.0f / (1.0f + __expf(-zf));
                float gg = 2.0f / (1.0f + __expf(-2.0f * zg)) - 1.0f;
                float og = 1.0f / (1.0f + __expf(-zo));
                float cn = fg * g_c[b * 1024 + u] + ig * gg;
                g_c[b * 1024 + u] = cn;
                float th = 2.0f / (1.0f + __expf(-2.0f * cn)) - 1.0f;
                hv[v] = og * th;
            }
            *(float2*)&y[((size_t)b * 512 + t) * 1024 + j * 8 + uq * 2] =
                make_float2(hv[0], hv[1]);
            __half hf2[2];
            hf2[0] = __float2half_rn(hv[0]);
            hf2[1] = __float2half_rn(hv[1]);
            *(uint32_t*)(g_htf[t + 1] + (size_t)b * 1024 + j * 8 + uq * 2) = *(uint32_t*)hf2;
        }

        // ---- grid barrier: release arrival, acquire poll ------------------
        __threadfence();
        __syncthreads();
        if (tid == 0) {
            red_release(&g_cnt[t]);
            while (ld_acq(&g_cnt[t]) < NCTA) { }
            __threadfence();
        }
        __syncthreads();
    }
}

// ---------------------------------------------------------------------------
extern "C" void kernel_launch(void* const* d_in, const int* in_sizes, int n_in,
                              void* d_out, int out_size)
{
    const float* x  = (const float*)d_in[0];
    const float* Wx = (const float*)d_in[1];
    const float* Wh = (const float*)d_in[2];
    const float* b  = (const float*)d_in[3];
    float* y = (float*)d_out;

    cudaFuncSetAttribute(xproj_kernel, cudaFuncAttributeMaxDynamicSharedMemorySize, 131072);
    cudaFuncSetAttribute(step_persist, cudaFuncAttributeMaxDynamicSharedMemorySize, ST_SMEM);

    init_kernel<<<64, 256>>>();
    pack_x_kernel<<<16384, 256>>>(x);
    pack_w_kernel<<<dim3(128, 32), 256>>>(Wx, 0);
    pack_w_kernel<<<dim3(128, 32), 256>>>(Wh, 1);
    xproj_kernel<<<dim3(32, 256), 256, 131072>>>(b);
    step_persist<<<NCTA, 256, ST_SMEM>>>(y);
}

// round 14
// speedup vs baseline: 2.1832x; 1.2692x over previous
#include <cuda_runtime.h>
#include <cuda_bf16.h>
#include <cuda_fp16.h>
#include <cstdint>

// dims: B=64, T=512, D=U=1024, 4U=4096
#define NCTA 128

// ---------------- scratch (__device__ globals) -----------------------------
__device__ __align__(16) __half g_xf[(size_t)32768 * 1024];    // x fp16
__device__ __align__(16) __half g_wxf[(size_t)4096 * 1024];    // Wx fp16 (permuted rows)
__device__ __align__(16) __half g_whfh[(size_t)4096 * 1024];   // Wh fp16 (permuted rows)
// write-once h history (fp16): step t reads [t], writes [t+1]
__device__ __align__(16) __half g_htf[513][64 * 1024];
__device__ float g_c[64 * 1024];                       // [b][u]
__device__ float g_xproj[(size_t)512 * 4096 * 64];     // [t][p][b], bias folded
__device__ int g_cnt[512];                              // per-step arrival counters

// ---------------- helpers --------------------------------------------------
__device__ __forceinline__ uint32_t smem_u32(const void* p) {
    uint32_t a;
    asm("{ .reg .u64 t; cvta.to.shared.u64 t, %1; cvt.u32.u64 %0, t; }" : "=r"(a) : "l"(p));
    return a;
}
__device__ __forceinline__ void cp16(uint32_t saddr, const void* g) {
    asm volatile("cp.async.cg.shared.global [%0], [%1], 16;" :: "r"(saddr), "l"(g) : "memory");
}
#define CP_COMMIT() asm volatile("cp.async.commit_group;" ::: "memory")
#define CP_WAIT1()  asm volatile("cp.async.wait_group 1;" ::: "memory")
#define CP_WAIT0()  asm volatile("cp.async.wait_group 0;" ::: "memory")

__device__ __forceinline__ void ldsm4(uint32_t* r, uint32_t addr) {
    asm volatile("ldmatrix.sync.aligned.m8n8.x4.shared.b16 {%0,%1,%2,%3}, [%4];"
        : "=r"(r[0]), "=r"(r[1]), "=r"(r[2]), "=r"(r[3]) : "r"(addr));
}
__device__ __forceinline__ void ldsm2(uint32_t* r, uint32_t addr) {
    asm volatile("ldmatrix.sync.aligned.m8n8.x2.shared.b16 {%0,%1}, [%2];"
        : "=r"(r[0]), "=r"(r[1]) : "r"(addr));
}
__device__ __forceinline__ void mma_f16(float* c, const uint32_t* a, uint32_t b0, uint32_t b1) {
    asm volatile("mma.sync.aligned.m16n8k16.row.col.f32.f16.f16.f32 "
        "{%0,%1,%2,%3}, {%4,%5,%6,%7}, {%8,%9}, {%0,%1,%2,%3};"
        : "+f"(c[0]), "+f"(c[1]), "+f"(c[2]), "+f"(c[3])
        : "r"(a[0]), "r"(a[1]), "r"(a[2]), "r"(a[3]), "r"(b0), "r"(b1));
}
__device__ __forceinline__ void red_release(int* p) {
    asm volatile("red.release.gpu.global.add.s32 [%0], 1;" :: "l"(p) : "memory");
}
__device__ __forceinline__ int ld_acq(const int* p) {
    int v; asm volatile("ld.acquire.gpu.global.b32 %0, [%1];" : "=r"(v) : "l"(p) : "memory"); return v;
}
// column permutation: p = j*32 + g*8 + uu  <->  gcol = g*1024 + j*8 + uu
__device__ __forceinline__ int gcol_of(int p) {
    return ((p >> 3) & 3) * 1024 + (p >> 5) * 8 + (p & 7);
}
// smem tile: rows of 128B (64 fp16), 16B chunks xor-swizzled by row
__device__ __forceinline__ uint32_t tadr(int row, int ch) {
    return (uint32_t)(row * 128 + ((ch ^ (row & 7)) << 4));
}

// ---------------- init -----------------------------------------------------
__global__ void init_kernel() {
    int i = blockIdx.x * 256 + threadIdx.x;
    uint4 z = make_uint4(0, 0, 0, 0);
    if (i < 8192) ((uint4*)g_htf[0])[i] = z;
    if (i < 16384) ((uint4*)g_c)[i] = z;
    if (i < 512) g_cnt[i] = 0;
}

// ---------------- packers --------------------------------------------------
__global__ void __launch_bounds__(256) pack_x_kernel(const float* __restrict__ x) {
    int u = blockIdx.x * 256 + threadIdx.x;           // 4194304
    int k8 = u & 127, m = u >> 7;
    int t = m >> 6, b = m & 63;
    const float* s = x + ((size_t)(b * 512 + t)) * 1024 + k8 * 8;
    float4 v0 = *(const float4*)s, v1 = *(const float4*)(s + 4);
    float v[8] = {v0.x, v0.y, v0.z, v0.w, v1.x, v1.y, v1.z, v1.w};
    __half hb[8];
#pragma unroll
    for (int i = 0; i < 8; i++) hb[i] = __float2half_rn(v[i]);
    *(uint4*)(g_xf + (size_t)m * 1024 + k8 * 8) = *(uint4*)hb;
}

__global__ void __launch_bounds__(256) pack_w_kernel(const float* __restrict__ W, int mode) {
    __shared__ float s[32][33];
    int p0 = blockIdx.x * 32, k0 = blockIdx.y * 32;
    int tid = threadIdx.x;
#pragma unroll
    for (int i = 0; i < 4; i++) {
        int idx = tid + i * 256;
        int kk = idx >> 5, pp = idx & 31;
        s[kk][pp] = W[(size_t)(k0 + kk) * 4096 + gcol_of(p0 + pp)];
    }
    __syncthreads();
    if (tid < 128) {
        int pp = tid >> 2, k8 = (tid & 3) * 8;
        size_t o = (size_t)(p0 + pp) * 1024 + k0 + k8;
        __half hb[8];
#pragma unroll
        for (int i = 0; i < 8; i++) hb[i] = __float2half_rn(s[k8 + i][pp]);
        *(uint4*)((mode ? g_whfh : g_wxf) + o) = *(uint4*)hb;
    }
}

// ---------------- x_proj GEMM (fp16 1-pass) --------------------------------
// stage (32KB): A 16KB | B 16KB; 2 stages = 64KB.
// Dynamic smem = 69632 B: the epilogue reuses [0, 67584) as sC[128][132] f32.
#define XP_SMEM 69632
__device__ __forceinline__ void xp_load(uint32_t sb, int s, int tid, int m0, int p0, int k0) {
    uint32_t st = sb + s * 32768;
#pragma unroll
    for (int rep = 0; rep < 4; rep++) {
        int c = tid + rep * 256;
        int row = c >> 3, ch = c & 7;
        uint32_t so = tadr(row, ch);
        size_t go = (size_t)k0 + ch * 8;
        cp16(st + so,         g_xf  + (size_t)(m0 + row) * 1024 + go);
        cp16(st + 16384 + so, g_wxf + (size_t)(p0 + row) * 1024 + go);
    }
}

__device__ __forceinline__ void xp_compute(uint32_t sb, int s, int lane,
                                           int m_off, int n_off, float C[16][4]) {
    uint32_t st = sb + s * 32768;
    int r15 = lane & 15, kh = lane >> 4;
#pragma unroll
    for (int ks = 0; ks < 4; ks++) {
        int ch = ks * 2 + kh;
        uint32_t aH[8], bH[16];
#pragma unroll
        for (int mt = 0; mt < 2; mt++)
            ldsm4(aH + mt * 4, st + tadr(m_off + mt * 16 + r15, ch));
#pragma unroll
        for (int nt = 0; nt < 4; nt++)
            ldsm4(bH + nt * 4, st + 16384 + tadr(n_off + nt * 16 + r15, ch));
#pragma unroll
        for (int mt = 0; mt < 2; mt++)
#pragma unroll
            for (int n8 = 0; n8 < 8; n8++) {
                int g = (n8 >> 1) * 4 + (n8 & 1);
                mma_f16(C[mt * 8 + n8], aH + mt * 4, bH[g], bH[g + 2]);
            }
    }
}

__global__ void __launch_bounds__(256, 1) xproj_kernel(const float* __restrict__ bias) {
    extern __shared__ __align__(16) unsigned char sm[];
    uint32_t sb = smem_u32(sm);
    int tid = threadIdx.x, lane = tid & 31, w = tid >> 5;
    int p0 = blockIdx.x * 128, m0 = blockIdx.y * 128;
    int m_off = (w & 3) * 32, n_off = (w >> 2) * 64;

    float C[16][4];
#pragma unroll
    for (int i = 0; i < 16; i++)
#pragma unroll
        for (int q = 0; q < 4; q++) C[i][q] = 0.0f;

    xp_load(sb, 0, tid, m0, p0, 0);  CP_COMMIT();
    xp_load(sb, 1, tid, m0, p0, 64); CP_COMMIT();
#pragma unroll 1
    for (int kt = 0; kt < 16; kt++) {
        if (kt < 15) { CP_WAIT1(); } else { CP_WAIT0(); }
        __syncthreads();
        xp_compute(sb, kt & 1, lane, m_off, n_off, C);
        __syncthreads();
        if (kt + 2 < 16) { xp_load(sb, kt & 1, tid, m0, p0, (kt + 2) * 64); CP_COMMIT(); }
    }

    float* sC = (float*)sm;  // [128][132] = 67584 B < XP_SMEM
    int r = lane >> 2, c2 = (lane & 3) * 2;
#pragma unroll
    for (int mt = 0; mt < 2; mt++)
#pragma unroll
        for (int n8 = 0; n8 < 8; n8++) {
            float* cf = C[mt * 8 + n8];
            int m = m_off + mt * 16 + r;
            int n = n_off + n8 * 8 + c2;
            sC[n * 132 + m]           = cf[0];
            sC[(n + 1) * 132 + m]     = cf[1];
            sC[n * 132 + m + 8]       = cf[2];
            sC[(n + 1) * 132 + m + 8] = cf[3];
        }
    __syncthreads();
    {
        int n = tid >> 1, tq = tid & 1;
        int p = p0 + n;
        float bv = bias[gcol_of(p)];
        float* dst = g_xproj + ((size_t)(blockIdx.y * 2 + tq) * 4096 + p) * 64;
        const float* src = sC + n * 132 + tq * 64;
#pragma unroll
        for (int i = 0; i < 16; i++) {
            float4 v = *(const float4*)(src + i * 4);
            v.x += bv; v.y += bv; v.z += bv; v.w += bv;
            *(float4*)(dst + i * 4) = v;
        }
    }
}

// ---------------- persistent recurrence (fp16 1-pass, Wh smem-resident) ----
// smem: A stages 2x16KB at 0/16384 | WH 64KB at 32768 | Xp 8KB at 98304.
#define WH_OFF 32768u
#define XP_OFF 98304u
#define ST_SMEM 106496

__device__ __forceinline__ void st_load_A(uint32_t sb, int s, int tid,
                                          const __half* hf, int k0) {
    uint32_t st = sb + s * 16384;
#pragma unroll
    for (int rep = 0; rep < 4; rep++) {          // A: 64 rows x 128 k
        int idx = tid + rep * 256;
        int c = idx >> 9, r = idx & 511;
        int row = r >> 3, ch = r & 7;
        cp16(st + c * 8192 + tadr(row, ch),
             hf + (size_t)row * 1024 + k0 + c * 64 + ch * 8);
    }
}

__device__ __forceinline__ void st_compute(uint32_t sb, int s, int kt, int lane,
                                           int m_off, int n_off, float C[2][4]) {
    uint32_t st = sb + s * 16384;
    uint32_t wh = sb + WH_OFF + (uint32_t)kt * 8192;
    int r15 = lane & 15, kh = lane >> 4;
#pragma unroll
    for (int sub = 0; sub < 2; sub++) {
        uint32_t Ab = st + sub * 8192;
        uint32_t Bb = wh + sub * 4096;
#pragma unroll
        for (int ks = 0; ks < 4; ks++) {
            int ch = ks * 2 + kh;
            uint32_t aH[8], bH[2];
#pragma unroll
            for (int mt = 0; mt < 2; mt++)
                ldsm4(aH + mt * 4, Ab + tadr(m_off + mt * 16 + r15, ch));
            ldsm2(bH, Bb + tadr(n_off + (r15 & 7), ks * 2 + (r15 >> 3)));
#pragma unroll
            for (int mt = 0; mt < 2; mt++)
                mma_f16(C[mt], aH + mt * 4, bH[0], bH[1]);
        }
    }
}

__global__ void __launch_bounds__(256, 1) step_persist(float* __restrict__ y) {
    extern __shared__ __align__(16) unsigned char sm[];
    uint32_t sb = smem_u32(sm);
    const int tid = threadIdx.x, lane = tid & 31, w = tid >> 5;
    const int j = blockIdx.x, p0 = j * 32;
    const int m_off = (w & 1) * 32, n_off = (w >> 1) * 8;

    // ---- preload Wh slice (32 p-rows x 1024 k fp16 = 64KB), layout matches
    //      the staged layout: chunk kt at WH_OFF + kt*8192 + sub*4096.
#pragma unroll
    for (int rep = 0; rep < 16; rep++) {
        int idx = tid + rep * 256;                 // 0..4095
        int kt = idx >> 9;
        int rest = idx & 511;
        int sub = rest >> 8, r = rest & 255;
        int row = r >> 3, ch = r & 7;
        cp16(sb + WH_OFF + kt * 8192 + sub * 4096 + tadr(row, ch),
             g_whfh + (size_t)(p0 + row) * 1024 + kt * 128 + sub * 64 + ch * 8);
    }
    CP_COMMIT(); CP_WAIT0();
    __syncthreads();

#pragma unroll 1
    for (int t = 0; t < 512; t++) {
        const __half* hf = g_htf[t];

        // x_proj slice (8KB) grouped into first commit group
        {
            const char* xpg = (const char*)(g_xproj + ((size_t)t * 4096 + p0) * 64);
#pragma unroll
            for (int rep = 0; rep < 2; rep++) {
                int c = tid + rep * 256;
                cp16(sb + XP_OFF + c * 16, xpg + c * 16);
            }
        }
        st_load_A(sb, 0, tid, hf, 0);   CP_COMMIT();
        st_load_A(sb, 1, tid, hf, 128); CP_COMMIT();

        float C[2][4];
#pragma unroll
        for (int i = 0; i < 2; i++)
#pragma unroll
            for (int q = 0; q < 4; q++) C[i][q] = 0.0f;

#pragma unroll 1
        for (int kt = 0; kt < 8; kt++) {
            if (kt < 7) { CP_WAIT1(); } else { CP_WAIT0(); }
            __syncthreads();
            st_compute(sb, kt & 1, kt, lane, m_off, n_off, C);
            __syncthreads();
            if (kt + 2 < 8) { st_load_A(sb, kt & 1, tid, hf, (kt + 2) * 128); CP_COMMIT(); }
        }

        // frags -> Zs[n][b] (Zs overlays A stage 0; all loads retired, synced)
        float* Zs = (float*)sm;                        // [32][66]
        const float* Xp = (const float*)(sm + XP_OFF); // [32 p][64 b]
        {
            int r = lane >> 2, c2 = (lane & 3) * 2;
#pragma unroll
            for (int mt = 0; mt < 2; mt++) {
                float* cf = C[mt];
                int m = m_off + mt * 16 + r;
                int n = n_off + c2;
                Zs[n * 66 + m]           = cf[0];
                Zs[(n + 1) * 66 + m]     = cf[1];
                Zs[n * 66 + m + 8]       = cf[2];
                Zs[(n + 1) * 66 + m + 8] = cf[3];
            }
        }
        __syncthreads();
        {
            int b = tid >> 2, uq = tid & 3;
            float hv[2];
#pragma unroll
            for (int v = 0; v < 2; v++) {
                int uu = uq * 2 + v, u = j * 8 + uu;
                float zi = Zs[uu * 66 + b]        + Xp[uu * 64 + b];
                float zf = Zs[(8 + uu) * 66 + b]  + Xp[(8 + uu) * 64 + b];
                float zg = Zs[(16 + uu) * 66 + b] + Xp[(16 + uu) * 64 + b];
                float zo = Zs[(24 + uu) * 66 + b] + Xp[(24 + uu) * 64 + b];
                float ig = 1.0f / (1.0f + __expf(-zi));
                float fg = 1.0f / (1.0f + __expf(-zf));
                float gg = 2.0f / (1.0f + __expf(-2.0f * zg)) - 1.0f;
                float og = 1.0f / (1.0f + __expf(-zo));
                float cn = fg * g_c[b * 1024 + u] + ig * gg;
                g_c[b * 1024 + u] = cn;
                float th = 2.0f / (1.0f + __expf(-2.0f * cn)) - 1.0f;
                hv[v] = og * th;
            }
            *(float2*)&y[((size_t)b * 512 + t) * 1024 + j * 8 + uq * 2] =
                make_float2(hv[0], hv[1]);
            __half hf2[2];
            hf2[0] = __float2half_rn(hv[0]);
            hf2[1] = __float2half_rn(hv[1]);
            *(uint32_t*)(g_htf[t + 1] + (size_t)b * 1024 + j * 8 + uq * 2) = *(uint32_t*)hf2;
        }

        // ---- grid barrier: release arrival, acquire poll ------------------
        __threadfence();
        __syncthreads();
        if (tid == 0) {
            red_release(&g_cnt[t]);
            while (ld_acq(&g_cnt[t]) < NCTA) { }
            __threadfence();
        }
        __syncthreads();
    }
}

// ---------------------------------------------------------------------------
extern "C" void kernel_launch(void* const* d_in, const int* in_sizes, int n_in,
                              void* d_out, int out_size)
{
    const float* x  = (const float*)d_in[0];
    const float* Wx = (const float*)d_in[1];
    const float* Wh = (const float*)d_in[2];
    const float* b  = (const float*)d_in[3];
    float* y = (float*)d_out;

    cudaFuncSetAttribute(xproj_kernel, cudaFuncAttributeMaxDynamicSharedMemorySize, XP_SMEM);
    cudaFuncSetAttribute(step_persist, cudaFuncAttributeMaxDynamicSharedMemorySize, ST_SMEM);

    init_kernel<<<64, 256>>>();
    pack_x_kernel<<<16384, 256>>>(x);
    pack_w_kernel<<<dim3(128, 32), 256>>>(Wx, 0);
    pack_w_kernel<<<dim3(128, 32), 256>>>(Wh, 1);
    xproj_kernel<<<dim3(32, 256), 256, XP_SMEM>>>(b);
    step_persist<<<NCTA, 256, ST_SMEM>>>(y);
}